// round 11
// baseline (speedup 1.0000x reference)
#include <cuda_runtime.h>
#include <mma.h>
#include <cstdint>

using namespace nvcuda;

// ---------------------------------------------------------------------------
// VisionSdpaAttention — v8: tcgen05 GEMMs + mma.sync attention with
// safe-bound softmax (exp2(s' - c_row), c_row = ||q'||*kmax; no online stats)
//   L=1024, B=8, C=1024, H=16, D=64
// ---------------------------------------------------------------------------

#if defined(__CUDA_ARCH_FEAT_SM103_ALL) || defined(__CUDA_ARCH_FEAT_SM100_ALL)
#define HAS_TCGEN05 1
#else
#define HAS_TCGEN05 0
#endif

__device__ float g_hs[8388608];               // tf32-rounded hidden_states
__device__ float g_wqkv[3145728];             // tf32-rounded Wqkv
__device__ float g_wo[1048576];               // tf32-rounded Wo
__device__ float g_qkv[25165824];             // (L*B, 3C)
__device__ float g_q[8388608];                // (B,H,L,D) tf32, scaled 0.125*log2(e)
__device__ float g_k[8388608];
__device__ float g_v[8388608];
__device__ float g_attn[8388608];             // (L*B, C) tf32-rounded
__device__ unsigned long long g_maskbits[131072];  // [B][16 kt][1024 rows]
__device__ float g_kmax[128];                 // per (b,h): max_k ||k||
__device__ int g_mask_mode;
__device__ int g_use_tc;

__device__ __forceinline__ float to_tf32(float x) {
    unsigned int u;
    asm("cvt.rna.tf32.f32 %0, %1;" : "=r"(u) : "f"(x));
    return __uint_as_float(u);
}
__device__ __forceinline__ void cp_async16(void* sptr, const void* gptr) {
    unsigned s = (unsigned)__cvta_generic_to_shared(sptr);
    asm volatile("cp.async.cg.shared.global [%0], [%1], 16;" :: "r"(s), "l"(gptr));
}
__device__ __forceinline__ void cp_async16s(uint32_t saddr, const void* gptr) {
    asm volatile("cp.async.cg.shared.global [%0], [%1], 16;" :: "r"(saddr), "l"(gptr));
}
__device__ __forceinline__ void cp_commit() {
    asm volatile("cp.async.commit_group;");
}
__device__ __forceinline__ void mma8(float* c, const unsigned* a, unsigned b0, unsigned b1) {
    asm volatile(
        "mma.sync.aligned.m16n8k8.row.col.f32.tf32.tf32.f32 "
        "{%0,%1,%2,%3},{%4,%5,%6,%7},{%8,%9},{%0,%1,%2,%3};"
        : "+f"(c[0]), "+f"(c[1]), "+f"(c[2]), "+f"(c[3])
        : "r"(a[0]), "r"(a[1]), "r"(a[2]), "r"(a[3]), "r"(b0), "r"(b1));
}
__device__ __forceinline__ uint32_t smem_u32(const void* p) {
    return (uint32_t)__cvta_generic_to_shared(p);
}

__global__ void probe_tc_kernel() { if (threadIdx.x == 0) g_use_tc = HAS_TCGEN05; }

// ---------------------------------------------------------------------------
// tf32 rounding copy
// ---------------------------------------------------------------------------
__global__ __launch_bounds__(256) void tf32_round_kernel(
    float* __restrict__ dst, const float* __restrict__ src, int n4)
{
    int i = blockIdx.x * 256 + threadIdx.x;
    if (i >= n4) return;
    float4 v = *((const float4*)src + i);
    v.x = to_tf32(v.x); v.y = to_tf32(v.y);
    v.z = to_tf32(v.z); v.w = to_tf32(v.w);
    *((float4*)dst + i) = v;
}

// ---------------------------------------------------------------------------
// Mask detection + bitpack -> layout [b][kt][row]
// ---------------------------------------------------------------------------
__global__ void detect_mask_mode_kernel(const unsigned char* __restrict__ m)
{
    __shared__ int s1, s23;
    const int tid = threadIdx.x;
    if (tid == 0) { s1 = 0; s23 = 0; }
    __syncthreads();
    bool o1 = false, o23 = false;
    for (int i = tid * 4; i < 16384; i += 1024) {
        if (m[i + 1] != 0) o1 = true;
        if (m[i + 2] != 0 || m[i + 3] != 0) o23 = true;
    }
    if (o1) atomicOr(&s1, 1);
    if (o23) atomicOr(&s23, 1);
    __syncthreads();
    if (tid == 0) g_mask_mode = s1 ? 0 : (s23 ? 2 : 1);
}

__global__ __launch_bounds__(256) void convert_mask_bits_kernel(const void* __restrict__ mp)
{
    const int idx = blockIdx.x * 256 + threadIdx.x;   // input word: (b*1024+row)*16+kt
    const int mode = g_mask_mode;
    unsigned long long bits = 0ULL;
    const size_t base = (size_t)idx * 64;
    if (mode == 0) {
        const uint4* p = (const uint4*)((const unsigned char*)mp + base);
#pragma unroll
        for (int wrd = 0; wrd < 4; wrd++) {
            uint4 v = p[wrd];
            unsigned ws[4] = {v.x, v.y, v.z, v.w};
#pragma unroll
            for (int q = 0; q < 4; q++)
#pragma unroll
                for (int by = 0; by < 4; by++)
                    if ((ws[q] >> (by * 8)) & 0xffu)
                        bits |= 1ULL << (wrd * 16 + q * 4 + by);
        }
    } else if (mode == 1) {
        const int* p = (const int*)mp + base;
#pragma unroll 8
        for (int j = 0; j < 64; j++)
            if (p[j] != 0) bits |= 1ULL << j;
    } else {
        const float* p = (const float*)mp + base;
#pragma unroll 8
        for (int j = 0; j < 64; j++)
            if (p[j] != 0.0f) bits |= 1ULL << j;
    }
    const int b = idx >> 14;
    const int row = (idx >> 4) & 1023;
    const int kt = idx & 15;
    g_maskbits[((size_t)b * 16 + kt) * 1024 + row] = bits;
}

// ---------------------------------------------------------------------------
// Per-head kmax
// ---------------------------------------------------------------------------
__global__ __launch_bounds__(256) void kmax_kernel()
{
    __shared__ float sred[8];
    const int bh = blockIdx.x;
    const int tid = threadIdx.x;
    float mx = 0.f;
    for (int r = tid; r < 1024; r += 256) {
        const float4* kr = (const float4*)(g_k + (size_t)bh * 65536 + r * 64);
        float s = 0.f;
#pragma unroll
        for (int f = 0; f < 16; f++) {
            float4 v = kr[f];
            s += v.x * v.x + v.y * v.y + v.z * v.z + v.w * v.w;
        }
        mx = fmaxf(mx, s);
    }
#pragma unroll
    for (int d = 16; d > 0; d >>= 1)
        mx = fmaxf(mx, __shfl_xor_sync(0xffffffffu, mx, d));
    if ((tid & 31) == 0) sred[tid >> 5] = mx;
    __syncthreads();
    if (tid < 8) {
        float v = sred[tid];
#pragma unroll
        for (int d = 4; d > 0; d >>= 1)
            v = fmaxf(v, __shfl_xor_sync(0xffu, v, d));
        if (tid == 0) g_kmax[bh] = sqrtf(v);
    }
}

// ===========================================================================
// tcgen05 helpers + GEMM (verified working in R9)
// ===========================================================================
#if HAS_TCGEN05
__device__ __forceinline__ uint32_t elect_one_pred() {
    uint32_t pred;
    asm volatile(
        "{\n\t.reg .pred p;\n\telect.sync _|p, 0xFFFFFFFF;\n\t"
        "selp.b32 %0, 1, 0, p;\n\t}" : "=r"(pred));
    return pred;
}
static __device__ __forceinline__ uint64_t make_desc_sw128(uint32_t addr) {
    return ((uint64_t)2u << 61) | ((uint64_t)1u << 46) | ((uint64_t)64u << 32)
         | ((uint64_t)1u << 16) | ((uint64_t)(addr >> 4) & 0x3FFFu);
}
__device__ __forceinline__ void tcgen05_mma_tf32_ss(
    uint32_t d_tmem, uint64_t a_desc, uint64_t b_desc, uint32_t idesc, bool enable_d)
{
    uint32_t en = enable_d ? 1u : 0u;
    asm volatile(
        "{\n\t.reg .pred p;\n\t"
        "setp.ne.u32 p, %5, 0;\n\t"
        "tcgen05.mma.cta_group::1.kind::tf32 [%0], %1, %2, %3, {%4, %4, %4, %4}, p;\n\t"
        "}"
        :: "r"(d_tmem), "l"(a_desc), "l"(b_desc), "r"(idesc), "r"(0u), "r"(en)
        : "memory");
}
#define TC_LD_X32(r, addr) \
    asm volatile( \
        "tcgen05.ld.sync.aligned.32x32b.x32.b32 " \
        "{%0, %1, %2, %3, %4, %5, %6, %7, " \
        " %8, %9, %10, %11, %12, %13, %14, %15, " \
        " %16, %17, %18, %19, %20, %21, %22, %23, " \
        " %24, %25, %26, %27, %28, %29, %30, %31}, [%32];" \
        : "=r"((r)[0]),  "=r"((r)[1]),  "=r"((r)[2]),  "=r"((r)[3]), \
          "=r"((r)[4]),  "=r"((r)[5]),  "=r"((r)[6]),  "=r"((r)[7]), \
          "=r"((r)[8]),  "=r"((r)[9]),  "=r"((r)[10]), "=r"((r)[11]), \
          "=r"((r)[12]), "=r"((r)[13]), "=r"((r)[14]), "=r"((r)[15]), \
          "=r"((r)[16]), "=r"((r)[17]), "=r"((r)[18]), "=r"((r)[19]), \
          "=r"((r)[20]), "=r"((r)[21]), "=r"((r)[22]), "=r"((r)[23]), \
          "=r"((r)[24]), "=r"((r)[25]), "=r"((r)[26]), "=r"((r)[27]), \
          "=r"((r)[28]), "=r"((r)[29]), "=r"((r)[30]), "=r"((r)[31]) \
        : "r"(addr))
#define MBAR_WAIT(mbar, parity) do {                                              \
    asm volatile(                                                                 \
        "{\n\t.reg .pred P1;\n\t"                                                 \
        "WAIT_LOOP_%=:\n\t"                                                       \
        "mbarrier.try_wait.parity.acquire.cta.shared::cta.b64 P1, [%0], %1, 0x989680;\n\t" \
        "@P1 bra.uni WAIT_DONE_%=;\n\t"                                           \
        "bra.uni WAIT_LOOP_%=;\n\t"                                               \
        "WAIT_DONE_%=:\n\t}"                                                      \
        :: "r"((uint32_t)(mbar)), "r"((uint32_t)(parity)) : "memory");            \
} while (0)
static constexpr uint32_t TC_IDESC_G =
    (1u << 4) | (2u << 7) | (2u << 10) | ((256u / 8) << 17) | ((128u / 16) << 24);
#endif

#define TCSTAGE 49152
#define TCB_OFF 16384

__global__ __launch_bounds__(128) void gemm_tc_tf32(
    const float* __restrict__ A, const float* __restrict__ B,
    float* __restrict__ C, int M, int N, int K)
{
#if HAS_TCGEN05
    extern __shared__ char smem[];
    const uint32_t sb = smem_u32(smem);
    const uint32_t ctrl = sb;
    const uint32_t data = (sb + 16 + 1023) & ~1023u;

    const int bm = blockIdx.y * 128;
    const int bn = blockIdx.x * 256;
    const int tid = threadIdx.x;
    const int wid = tid >> 5;
    const int lane = tid & 31;

    if (wid == 0) {
        asm volatile("tcgen05.alloc.cta_group::1.sync.aligned.shared::cta.b32 [%0], %1;"
            :: "r"(ctrl), "r"(256u) : "memory");
        asm volatile("tcgen05.relinquish_alloc_permit.cta_group::1.sync.aligned;");
    }
    __syncthreads();
    uint32_t tmem;
    asm volatile("ld.shared.b32 %0, [%1];" : "=r"(tmem) : "r"(ctrl));
    if (tid == 0)
        asm volatile("mbarrier.init.shared.b64 [%0], %1;" :: "r"(ctrl + 8), "r"(1u) : "memory");
    __syncthreads();

    const int nk = K / 32;

    auto load_chunk = [&](int it) {
        const uint32_t st = data + (uint32_t)(it & 1) * TCSTAGE;
        const int k0 = it * 32;
#pragma unroll
        for (int i = 0; i < 8; i++) {
            int e = tid + i * 128;
            int r = e >> 3, c = e & 7;
            uint32_t byte = (uint32_t)(r * 128 + c * 16);
            uint32_t sw = byte ^ ((byte >> 3) & 0x70u);
            cp_async16s(st + sw, A + (size_t)(bm + r) * K + k0 + c * 4);
        }
#pragma unroll
        for (int i = 0; i < 16; i++) {
            int e = tid + i * 128;
            int r = e >> 3, c = e & 7;
            uint32_t byte = (uint32_t)(r * 128 + c * 16);
            uint32_t sw = byte ^ ((byte >> 3) & 0x70u);
            cp_async16s(st + TCB_OFF + sw, B + (size_t)(bn + r) * K + k0 + c * 4);
        }
        cp_commit();
    };

    load_chunk(0);

    for (int it = 0; it < nk; it++) {
        asm volatile("cp.async.wait_group 0;");
        __syncthreads();
        asm volatile("fence.proxy.async.shared::cta;" ::: "memory");
        if (wid == 0) {
            const uint32_t st = data + (uint32_t)(it & 1) * TCSTAGE;
            uint64_t ad = make_desc_sw128(st);
            uint64_t bd = make_desc_sw128(st + TCB_OFF);
            if (elect_one_pred()) {
#pragma unroll
                for (int ks = 0; ks < 4; ks++)
                    tcgen05_mma_tf32_ss(tmem, ad + ks * 2, bd + ks * 2, TC_IDESC_G,
                                        (it != 0) || (ks != 0));
                asm volatile(
                    "tcgen05.commit.cta_group::1.mbarrier::arrive::one.shared::cluster.b64 [%0];"
                    :: "r"(ctrl + 8) : "memory");
            }
        }
        if (it + 1 < nk) load_chunk(it + 1);
        MBAR_WAIT(ctrl + 8, it & 1);
    }

    asm volatile("tcgen05.fence::after_thread_sync;" ::: "memory");

    {
        float* Crow = C + (size_t)(bm + wid * 32 + lane) * N + bn;
#pragma unroll
        for (int bt = 0; bt < 8; bt++) {
            uint32_t r32[32];
            TC_LD_X32(r32, tmem + bt * 32);
            asm volatile("tcgen05.wait::ld.sync.aligned;" ::: "memory");
#pragma unroll
            for (int q = 0; q < 8; q++) {
                float4 o;
                o.x = __uint_as_float(r32[q * 4 + 0]);
                o.y = __uint_as_float(r32[q * 4 + 1]);
                o.z = __uint_as_float(r32[q * 4 + 2]);
                o.w = __uint_as_float(r32[q * 4 + 3]);
                *(float4*)(Crow + bt * 32 + q * 4) = o;
            }
        }
    }

    __syncthreads();
    if (tid == 0)
        asm volatile("mbarrier.inval.shared.b64 [%0];" :: "r"(ctrl + 8) : "memory");
    __syncthreads();
    if (wid == 0)
        asm volatile("tcgen05.dealloc.cta_group::1.sync.aligned.b32 %0, %1;"
            :: "r"(tmem), "r"(256u));
#else
    (void)A; (void)B; (void)C; (void)M; (void)N; (void)K;
#endif
}

// ===========================================================================
// wmma GEMM fallback (non-'a' cubin only)
// ===========================================================================
#define GLDA 36
#define ASTG (128 * GLDA)
#define BSTG (256 * GLDA)

__global__ __launch_bounds__(256) void gemm_wmma_tf32(
    const float* __restrict__ A, const float* __restrict__ B,
    float* __restrict__ C, int M, int N, int K)
{
    if (g_use_tc) return;

    extern __shared__ float sg[];
    float* Asb[2] = { sg,            sg + ASTG };
    float* Bsb[2] = { sg + 2 * ASTG, sg + 2 * ASTG + BSTG };

    const int bm = blockIdx.y * 128;
    const int bn = blockIdx.x * 256;
    const int tid = threadIdx.x;
    const int wid = tid >> 5;
    const int warpM = wid & 1;
    const int warpN = wid >> 1;

    wmma::fragment<wmma::accumulator, 16, 16, 8, float> acc[4][4];
#pragma unroll
    for (int i = 0; i < 4; i++)
#pragma unroll
        for (int j = 0; j < 4; j++) wmma::fill_fragment(acc[i][j], 0.0f);

    const int nk = K / 32;
    auto load_chunk = [&](int it) {
        const int k0 = it * 32;
        float* As = Asb[it & 1];
        float* Bs = Bsb[it & 1];
#pragma unroll
        for (int i = 0; i < 4; i++) {
            int e = tid + i * 256;
            int r = e >> 3, c = (e & 7) * 4;
            cp_async16(As + r * GLDA + c, A + (size_t)(bm + r) * K + k0 + c);
        }
#pragma unroll
        for (int i = 0; i < 8; i++) {
            int e = tid + i * 256;
            int r = e >> 3, c = (e & 7) * 4;
            cp_async16(Bs + r * GLDA + c, B + (size_t)(bn + r) * K + k0 + c);
        }
        cp_commit();
    };
    load_chunk(0);
    for (int it = 0; it < nk; it++) {
        asm volatile("cp.async.wait_group 0;");
        __syncthreads();
        if (it + 1 < nk) load_chunk(it + 1);
        const float* As = Asb[it & 1];
        const float* Bs = Bsb[it & 1];
#pragma unroll
        for (int ks = 0; ks < 4; ks++) {
            wmma::fragment<wmma::matrix_a, 16, 16, 8, wmma::precision::tf32, wmma::row_major> af[4];
            wmma::fragment<wmma::matrix_b, 16, 16, 8, wmma::precision::tf32, wmma::col_major> bf[4];
#pragma unroll
            for (int i = 0; i < 4; i++)
                wmma::load_matrix_sync(af[i], As + (warpM * 64 + i * 16) * GLDA + ks * 8, GLDA);
#pragma unroll
            for (int j = 0; j < 4; j++)
                wmma::load_matrix_sync(bf[j], Bs + (warpN * 64 + j * 16) * GLDA + ks * 8, GLDA);
#pragma unroll
            for (int i = 0; i < 4; i++)
#pragma unroll
                for (int j = 0; j < 4; j++)
                    wmma::mma_sync(acc[i][j], af[i], bf[j], acc[i][j]);
        }
    }
#pragma unroll
    for (int i = 0; i < 4; i++)
#pragma unroll
        for (int j = 0; j < 4; j++)
            wmma::store_matrix_sync(
                C + (size_t)(bm + warpM * 64 + i * 16) * N + bn + warpN * 64 + j * 16,
                acc[i][j], N, wmma::mem_row_major);
}

// ---------------------------------------------------------------------------
// RoPE + bias + transpose; q scaled by 0.125*log2(e); tf32 stores
// ---------------------------------------------------------------------------
__global__ __launch_bounds__(256) void rope_bias_transpose_kernel(
    const float* __restrict__ rpe, const float* __restrict__ bq)
{
    __shared__ float cs[32], sn[32];
    const int m = blockIdx.x;   // l*8 + b
    const int l = m >> 3;
    const int b = m & 7;
    const int tid = threadIdx.x;
    if (tid < 32) {
        float a = rpe[l * 32 + tid];
        cs[tid] = cosf(a);
        sn[tid] = sinf(a);
    }
    __syncthreads();
    const float* src = g_qkv + (size_t)m * 3072;
    for (int r = tid; r < 3072; r += 256) {
        int which = r >> 10;
        int hh = (r >> 6) & 15;
        int d = r & 63;
        float x = src[r] + bq[r];
        float val;
        if (which < 2) {
            float xp = src[r ^ 1] + bq[r ^ 1];
            float c = cs[d & 31];
            float s = sn[d & 31];
            val = x * c + ((d & 1) ? xp : -xp) * s;
        } else {
            val = x;
        }
        if (which == 0) val *= 0.125f * 1.44269504f;   // scale * log2(e)
        float* dst = (which == 0) ? g_q : (which == 1) ? g_k : g_v;
        dst[(((size_t)(b * 16 + hh)) * 1024 + l) * 64 + d] = to_tf32(val);
    }
}

// ===========================================================================
// Flash attention, mma.sync tf32, SAFE-BOUND softmax:
//   p = exp2(s' - c_row), c_row = ||q'_row|| * kmax[bh]  (s' has log2e folded)
// No online stats; row sums accumulate per-thread, reduced once at end.
// grid (128 bh, 8 qt of 128 rows), 128 threads (4 warps, 32 rows/warp).
// ===========================================================================
#define AKL 68
#define AVL 72
#define QSTG (128 * AKL)
#define KSTG (64 * AKL)
#define VSTG (64 * AVL)
// smem: Qs(=P) + 2*K + 2*V + 128 norms
#define ATT_FB_SMEM ((QSTG + 2 * KSTG + 2 * VSTG + 128) * (int)sizeof(float))

__global__ __launch_bounds__(128) void attn_tf32_reg()
{
    extern __shared__ float sm[];
    float* Qs = sm;
    float* Ksb[2] = { sm + QSTG,            sm + QSTG + KSTG };
    float* Vsb[2] = { sm + QSTG + 2 * KSTG, sm + QSTG + 2 * KSTG + VSTG };
    float* sNorm = sm + QSTG + 2 * KSTG + 2 * VSTG;   // 128 row shifts

    const int bh = blockIdx.x;
    const int b = bh >> 4;
    const int h = bh & 15;
    const int qt = blockIdx.y;
    const int tid = threadIdx.x;
    const int w = tid >> 5;
    const int lane = tid & 31;
    const int g = lane >> 2;
    const int t = lane & 3;

    const float* Kg = g_k + (size_t)bh * 65536;
    const float* Vg = g_v + (size_t)bh * 65536;

    auto load_kv = [&](int kt) {
        float* Kd = Ksb[kt & 1];
        float* Vd = Vsb[kt & 1];
        const size_t off = (size_t)kt * 4096;
#pragma unroll
        for (int i = 0; i < 8; i++) {
            int e = tid + i * 128;
            int r = e >> 4, c = (e & 15) * 4;
            cp_async16(Kd + r * AKL + c, Kg + off + (size_t)r * 64 + c);
            cp_async16(Vd + r * AVL + c, Vg + off + (size_t)r * 64 + c);
        }
        cp_commit();
    };
    load_kv(0);

    {
        const float* Qg = g_q + ((size_t)bh * 1024 + qt * 128) * 64;
#pragma unroll
        for (int i = 0; i < 16; i++) {
            int e = tid + i * 128;
            int r = e >> 4, c = (e & 15) * 4;
            float4 v = *(const float4*)(Qg + r * 64 + c);
            *(float4*)(Qs + r * AKL + c) = v;
        }
    }
    __syncthreads();

    // per-row softmax shift: sNorm[r] = ||q'_r|| * kmax + eps
    {
        float qq = 0.f;
        const float4* qr = (const float4*)(Qs + tid * AKL);
#pragma unroll
        for (int f = 0; f < 16; f++) {
            float4 v = qr[f];
            qq += v.x * v.x + v.y * v.y + v.z * v.z + v.w * v.w;
        }
        sNorm[tid] = sqrtf(qq) * g_kmax[bh] + 1e-3f;
    }

    unsigned qa[2][8][4];
#pragma unroll
    for (int rf = 0; rf < 2; rf++) {
        const float* Qw = Qs + (w * 32 + rf * 16) * AKL;
#pragma unroll
        for (int ks = 0; ks < 8; ks++) {
            qa[rf][ks][0] = __float_as_uint(Qw[g * AKL + ks * 8 + t]);
            qa[rf][ks][1] = __float_as_uint(Qw[(g + 8) * AKL + ks * 8 + t]);
            qa[rf][ks][2] = __float_as_uint(Qw[g * AKL + ks * 8 + t + 4]);
            qa[rf][ks][3] = __float_as_uint(Qw[(g + 8) * AKL + ks * 8 + t + 4]);
        }
    }
    __syncthreads();   // norms visible; Qs becomes P strips

    float csh[2][2];
#pragma unroll
    for (int rf = 0; rf < 2; rf++) {
        csh[rf][0] = sNorm[w * 32 + rf * 16 + g];
        csh[rf][1] = sNorm[w * 32 + rf * 16 + 8 + g];
    }

    float o[2][8][4];
#pragma unroll
    for (int rf = 0; rf < 2; rf++)
#pragma unroll
        for (int j = 0; j < 8; j++)
            o[rf][j][0] = o[rf][j][1] = o[rf][j][2] = o[rf][j][3] = 0.f;
    float psum[2][2] = {{0.f, 0.f}, {0.f, 0.f}};

    const int qrow = qt * 128 + w * 32 + g;
    float* Pw = Qs + (w * 32) * AKL;

    for (int kt = 0; kt < 16; kt++) {
        asm volatile("cp.async.wait_group 0;");
        __syncthreads();
        if (kt + 1 < 16) load_kv(kt + 1);

        const float* Ks = Ksb[kt & 1];
        const float* Vs = Vsb[kt & 1];

        // S = Q K^T
        float s[2][8][4];
#pragma unroll
        for (int j = 0; j < 8; j++) {
            s[0][j][0] = s[0][j][1] = s[0][j][2] = s[0][j][3] = 0.f;
            s[1][j][0] = s[1][j][1] = s[1][j][2] = s[1][j][3] = 0.f;
#pragma unroll
            for (int ks = 0; ks < 8; ks++) {
                unsigned b0 = __float_as_uint(Ks[(j * 8 + g) * AKL + ks * 8 + t]);
                unsigned b1 = __float_as_uint(Ks[(j * 8 + g) * AKL + ks * 8 + t + 4]);
                mma8(s[0][j], qa[0][ks], b0, b1);
                mma8(s[1][j], qa[1][ks], b0, b1);
            }
        }

        // safe-bound softmax: p = exp2(s - c) if mask else 0
        const size_t mbi = ((size_t)b * 16 + kt) * 1024;
#pragma unroll
        for (int rf = 0; rf < 2; rf++) {
            const unsigned long long mb0 = g_maskbits[mbi + qrow + rf * 16];
            const unsigned long long mb1 = g_maskbits[mbi + qrow + rf * 16 + 8];
            float* Prf = Pw + rf * 16 * AKL;
#pragma unroll
            for (int j = 0; j < 8; j++) {
                int c0 = j * 8 + t * 2;
                float p0 = ((mb0 >> c0) & 1ULL)       ? exp2f(s[rf][j][0] - csh[rf][0]) : 0.f;
                float p1 = ((mb0 >> (c0 + 1)) & 1ULL) ? exp2f(s[rf][j][1] - csh[rf][0]) : 0.f;
                float p2 = ((mb1 >> c0) & 1ULL)       ? exp2f(s[rf][j][2] - csh[rf][1]) : 0.f;
                float p3 = ((mb1 >> (c0 + 1)) & 1ULL) ? exp2f(s[rf][j][3] - csh[rf][1]) : 0.f;
                psum[rf][0] += p0 + p1;
                psum[rf][1] += p2 + p3;
                *(float2*)(Prf + g * AKL + j * 8 + t * 2) =
                    make_float2(to_tf32(p0), to_tf32(p1));
                *(float2*)(Prf + (g + 8) * AKL + j * 8 + t * 2) =
                    make_float2(to_tf32(p2), to_tf32(p3));
            }
        }
        __syncwarp();

        // O += P V
#pragma unroll
        for (int ks = 0; ks < 8; ks++) {
            unsigned pa[2][4];
#pragma unroll
            for (int rf = 0; rf < 2; rf++) {
                const float* Prf = Pw + rf * 16 * AKL;
                pa[rf][0] = __float_as_uint(Prf[g * AKL + ks * 8 + t]);
                pa[rf][1] = __float_as_uint(Prf[(g + 8) * AKL + ks * 8 + t]);
                pa[rf][2] = __float_as_uint(Prf[g * AKL + ks * 8 + t + 4]);
                pa[rf][3] = __float_as_uint(Prf[(g + 8) * AKL + ks * 8 + t + 4]);
            }
#pragma unroll
            for (int j = 0; j < 8; j++) {
                unsigned b0 = __float_as_uint(Vs[(ks * 8 + t) * AVL + j * 8 + g]);
                unsigned b1 = __float_as_uint(Vs[(ks * 8 + t + 4) * AVL + j * 8 + g]);
                mma8(o[0][j], pa[0], b0, b1);
                mma8(o[1][j], pa[1], b0, b1);
            }
        }
        __syncwarp();
    }

    // single end-of-kernel row-sum reduction (quad)
#pragma unroll
    for (int rf = 0; rf < 2; rf++)
#pragma unroll
        for (int hf = 0; hf < 2; hf++) {
            float v = psum[rf][hf];
            v += __shfl_xor_sync(0xffffffffu, v, 1);
            v += __shfl_xor_sync(0xffffffffu, v, 2);
            psum[rf][hf] = v;
        }

#pragma unroll
    for (int rf = 0; rf < 2; rf++) {
        const float inv0 = 1.f / psum[rf][0], inv1 = 1.f / psum[rf][1];
        const int lq0 = qt * 128 + w * 32 + rf * 16 + g;
#pragma unroll
        for (int j = 0; j < 8; j++) {
            *(float2*)(g_attn + ((size_t)lq0 * 8 + b) * 1024 + h * 64 + j * 8 + t * 2) =
                make_float2(to_tf32(o[rf][j][0] * inv0), to_tf32(o[rf][j][1] * inv0));
            *(float2*)(g_attn + ((size_t)(lq0 + 8) * 8 + b) * 1024 + h * 64 + j * 8 + t * 2) =
                make_float2(to_tf32(o[rf][j][2] * inv1), to_tf32(o[rf][j][3] * inv1));
        }
    }
}

// ---------------------------------------------------------------------------
// Final bias add
// ---------------------------------------------------------------------------
__global__ __launch_bounds__(256) void bias_add_kernel(float* __restrict__ out,
                                                       const float* __restrict__ bo)
{
    const int m = blockIdx.x;
    const int c = threadIdx.x * 4;
    float4 o = *(float4*)(out + (size_t)m * 1024 + c);
    float4 bb = *(const float4*)(bo + c);
    o.x += bb.x; o.y += bb.y; o.z += bb.z; o.w += bb.w;
    *(float4*)(out + (size_t)m * 1024 + c) = o;
}

// ---------------------------------------------------------------------------
// Launch
// ---------------------------------------------------------------------------
extern "C" void kernel_launch(void* const* d_in, const int* in_sizes, int n_in,
                              void* d_out, int out_size)
{
    const float* hs   = (const float*)d_in[0];
    const float* rpe  = (const float*)d_in[1];
    const void* maskp = d_in[2];
    const float* Wqkv = (const float*)d_in[3];
    const float* bqkv = (const float*)d_in[4];
    const float* Wo   = (const float*)d_in[5];
    const float* bo   = (const float*)d_in[6];
    float* out        = (float*)d_out;

    float *hs_p, *wqkv_p, *wo_p, *qkv_p, *attn_p;
    cudaGetSymbolAddress((void**)&hs_p, g_hs);
    cudaGetSymbolAddress((void**)&wqkv_p, g_wqkv);
    cudaGetSymbolAddress((void**)&wo_p, g_wo);
    cudaGetSymbolAddress((void**)&qkv_p, g_qkv);
    cudaGetSymbolAddress((void**)&attn_p, g_attn);

    probe_tc_kernel<<<1, 32>>>();
    detect_mask_mode_kernel<<<1, 256>>>((const unsigned char*)maskp);
    convert_mask_bits_kernel<<<131072 / 256, 256>>>(maskp);
    tf32_round_kernel<<<(8388608 / 4) / 256, 256>>>(hs_p, hs, 8388608 / 4);
    tf32_round_kernel<<<(3145728 / 4) / 256, 256>>>(wqkv_p, Wqkv, 3145728 / 4);
    tf32_round_kernel<<<(1048576 / 4) / 256, 256>>>(wo_p, Wo, 1048576 / 4);

    const int tc_smem = 2048 + 2 * TCSTAGE;
    const int wm_smem = 2 * (ASTG + BSTG) * (int)sizeof(float);
    cudaFuncSetAttribute(gemm_tc_tf32,
                         cudaFuncAttributeMaxDynamicSharedMemorySize, tc_smem);
    cudaFuncSetAttribute(gemm_wmma_tf32,
                         cudaFuncAttributeMaxDynamicSharedMemorySize, wm_smem);

    // Stage 1: QKV projection (dual path)
    {
        dim3 grid(3072 / 256, 8192 / 128);
        gemm_tc_tf32<<<grid, 128, tc_smem>>>(hs_p, wqkv_p, qkv_p, 8192, 3072, 1024);
        gemm_wmma_tf32<<<grid, 256, wm_smem>>>(hs_p, wqkv_p, qkv_p, 8192, 3072, 1024);
    }

    // Stage 2: RoPE + bqkv + transpose ; kmax
    rope_bias_transpose_kernel<<<8192, 256>>>(rpe, bqkv);
    kmax_kernel<<<128, 256>>>();

    // Stage 3: attention (mma.sync, safe-bound softmax)
    {
        cudaFuncSetAttribute(attn_tf32_reg,
                             cudaFuncAttributeMaxDynamicSharedMemorySize, ATT_FB_SMEM);
        dim3 grid(128, 8);
        attn_tf32_reg<<<grid, 128, ATT_FB_SMEM>>>();
    }

    // Stage 4: output projection (dual path) + bias
    {
        dim3 grid(1024 / 256, 8192 / 128);
        gemm_tc_tf32<<<grid, 128, tc_smem>>>(attn_p, wo_p, out, 8192, 1024, 1024);
        gemm_wmma_tf32<<<grid, 256, wm_smem>>>(attn_p, wo_p, out, 8192, 1024, 1024);
        bias_add_kernel<<<8192, 256>>>(out, bo);
    }
}

// round 12
// speedup vs baseline: 1.1044x; 1.1044x over previous
#include <cuda_runtime.h>
#include <mma.h>
#include <cstdint>

using namespace nvcuda;

// ---------------------------------------------------------------------------
// VisionSdpaAttention — v9: tcgen05 GEMMs + mma.sync attention with
// safe-bound softmax using raw MUFU ex2.approx (flag-independent single instr)
//   L=1024, B=8, C=1024, H=16, D=64
// ---------------------------------------------------------------------------

#if defined(__CUDA_ARCH_FEAT_SM103_ALL) || defined(__CUDA_ARCH_FEAT_SM100_ALL)
#define HAS_TCGEN05 1
#else
#define HAS_TCGEN05 0
#endif

__device__ float g_hs[8388608];               // tf32-rounded hidden_states
__device__ float g_wqkv[3145728];             // tf32-rounded Wqkv
__device__ float g_wo[1048576];               // tf32-rounded Wo
__device__ float g_qkv[25165824];             // (L*B, 3C)
__device__ float g_q[8388608];                // (B,H,L,D) tf32, scaled 0.125*log2(e)
__device__ float g_k[8388608];
__device__ float g_v[8388608];
__device__ float g_attn[8388608];             // (L*B, C) tf32-rounded
__device__ unsigned long long g_maskbits[131072];  // [B][16 kt][1024 rows]
__device__ float g_kmax[128];                 // per (b,h): max_k ||k||
__device__ int g_mask_mode;
__device__ int g_use_tc;

__device__ __forceinline__ float to_tf32(float x) {
    unsigned int u;
    asm("cvt.rna.tf32.f32 %0, %1;" : "=r"(u) : "f"(x));
    return __uint_as_float(u);
}
__device__ __forceinline__ float ex2_fast(float x) {
    float r;
    asm("ex2.approx.ftz.f32 %0, %1;" : "=f"(r) : "f"(x));
    return r;
}
__device__ __forceinline__ void cp_async16(void* sptr, const void* gptr) {
    unsigned s = (unsigned)__cvta_generic_to_shared(sptr);
    asm volatile("cp.async.cg.shared.global [%0], [%1], 16;" :: "r"(s), "l"(gptr));
}
__device__ __forceinline__ void cp_async16s(uint32_t saddr, const void* gptr) {
    asm volatile("cp.async.cg.shared.global [%0], [%1], 16;" :: "r"(saddr), "l"(gptr));
}
__device__ __forceinline__ void cp_commit() {
    asm volatile("cp.async.commit_group;");
}
__device__ __forceinline__ void mma8(float* c, const unsigned* a, unsigned b0, unsigned b1) {
    asm volatile(
        "mma.sync.aligned.m16n8k8.row.col.f32.tf32.tf32.f32 "
        "{%0,%1,%2,%3},{%4,%5,%6,%7},{%8,%9},{%0,%1,%2,%3};"
        : "+f"(c[0]), "+f"(c[1]), "+f"(c[2]), "+f"(c[3])
        : "r"(a[0]), "r"(a[1]), "r"(a[2]), "r"(a[3]), "r"(b0), "r"(b1));
}
__device__ __forceinline__ uint32_t smem_u32(const void* p) {
    return (uint32_t)__cvta_generic_to_shared(p);
}

__global__ void probe_tc_kernel() { if (threadIdx.x == 0) g_use_tc = HAS_TCGEN05; }

// ---------------------------------------------------------------------------
// tf32 rounding copy
// ---------------------------------------------------------------------------
__global__ __launch_bounds__(256) void tf32_round_kernel(
    float* __restrict__ dst, const float* __restrict__ src, int n4)
{
    int i = blockIdx.x * 256 + threadIdx.x;
    if (i >= n4) return;
    float4 v = *((const float4*)src + i);
    v.x = to_tf32(v.x); v.y = to_tf32(v.y);
    v.z = to_tf32(v.z); v.w = to_tf32(v.w);
    *((float4*)dst + i) = v;
}

// ---------------------------------------------------------------------------
// Mask detection + bitpack -> layout [b][kt][row]
// ---------------------------------------------------------------------------
__global__ void detect_mask_mode_kernel(const unsigned char* __restrict__ m)
{
    __shared__ int s1, s23;
    const int tid = threadIdx.x;
    if (tid == 0) { s1 = 0; s23 = 0; }
    __syncthreads();
    bool o1 = false, o23 = false;
    for (int i = tid * 4; i < 16384; i += 1024) {
        if (m[i + 1] != 0) o1 = true;
        if (m[i + 2] != 0 || m[i + 3] != 0) o23 = true;
    }
    if (o1) atomicOr(&s1, 1);
    if (o23) atomicOr(&s23, 1);
    __syncthreads();
    if (tid == 0) g_mask_mode = s1 ? 0 : (s23 ? 2 : 1);
}

__global__ __launch_bounds__(256) void convert_mask_bits_kernel(const void* __restrict__ mp)
{
    const int idx = blockIdx.x * 256 + threadIdx.x;   // input word: (b*1024+row)*16+kt
    const int mode = g_mask_mode;
    unsigned long long bits = 0ULL;
    const size_t base = (size_t)idx * 64;
    if (mode == 0) {
        const uint4* p = (const uint4*)((const unsigned char*)mp + base);
#pragma unroll
        for (int wrd = 0; wrd < 4; wrd++) {
            uint4 v = p[wrd];
            unsigned ws[4] = {v.x, v.y, v.z, v.w};
#pragma unroll
            for (int q = 0; q < 4; q++)
#pragma unroll
                for (int by = 0; by < 4; by++)
                    if ((ws[q] >> (by * 8)) & 0xffu)
                        bits |= 1ULL << (wrd * 16 + q * 4 + by);
        }
    } else if (mode == 1) {
        const int* p = (const int*)mp + base;
#pragma unroll 8
        for (int j = 0; j < 64; j++)
            if (p[j] != 0) bits |= 1ULL << j;
    } else {
        const float* p = (const float*)mp + base;
#pragma unroll 8
        for (int j = 0; j < 64; j++)
            if (p[j] != 0.0f) bits |= 1ULL << j;
    }
    const int b = idx >> 14;
    const int row = (idx >> 4) & 1023;
    const int kt = idx & 15;
    g_maskbits[((size_t)b * 16 + kt) * 1024 + row] = bits;
}

// ---------------------------------------------------------------------------
// Per-head kmax
// ---------------------------------------------------------------------------
__global__ __launch_bounds__(256) void kmax_kernel()
{
    __shared__ float sred[8];
    const int bh = blockIdx.x;
    const int tid = threadIdx.x;
    float mx = 0.f;
    for (int r = tid; r < 1024; r += 256) {
        const float4* kr = (const float4*)(g_k + (size_t)bh * 65536 + r * 64);
        float s = 0.f;
#pragma unroll
        for (int f = 0; f < 16; f++) {
            float4 v = kr[f];
            s += v.x * v.x + v.y * v.y + v.z * v.z + v.w * v.w;
        }
        mx = fmaxf(mx, s);
    }
#pragma unroll
    for (int d = 16; d > 0; d >>= 1)
        mx = fmaxf(mx, __shfl_xor_sync(0xffffffffu, mx, d));
    if ((tid & 31) == 0) sred[tid >> 5] = mx;
    __syncthreads();
    if (tid < 8) {
        float v = sred[tid];
#pragma unroll
        for (int d = 4; d > 0; d >>= 1)
            v = fmaxf(v, __shfl_xor_sync(0xffu, v, d));
        if (tid == 0) g_kmax[bh] = sqrtf(v);
    }
}

// ===========================================================================
// tcgen05 helpers + GEMM (verified working in R9)
// ===========================================================================
#if HAS_TCGEN05
__device__ __forceinline__ uint32_t elect_one_pred() {
    uint32_t pred;
    asm volatile(
        "{\n\t.reg .pred p;\n\telect.sync _|p, 0xFFFFFFFF;\n\t"
        "selp.b32 %0, 1, 0, p;\n\t}" : "=r"(pred));
    return pred;
}
static __device__ __forceinline__ uint64_t make_desc_sw128(uint32_t addr) {
    return ((uint64_t)2u << 61) | ((uint64_t)1u << 46) | ((uint64_t)64u << 32)
         | ((uint64_t)1u << 16) | ((uint64_t)(addr >> 4) & 0x3FFFu);
}
__device__ __forceinline__ void tcgen05_mma_tf32_ss(
    uint32_t d_tmem, uint64_t a_desc, uint64_t b_desc, uint32_t idesc, bool enable_d)
{
    uint32_t en = enable_d ? 1u : 0u;
    asm volatile(
        "{\n\t.reg .pred p;\n\t"
        "setp.ne.u32 p, %5, 0;\n\t"
        "tcgen05.mma.cta_group::1.kind::tf32 [%0], %1, %2, %3, {%4, %4, %4, %4}, p;\n\t"
        "}"
        :: "r"(d_tmem), "l"(a_desc), "l"(b_desc), "r"(idesc), "r"(0u), "r"(en)
        : "memory");
}
#define TC_LD_X32(r, addr) \
    asm volatile( \
        "tcgen05.ld.sync.aligned.32x32b.x32.b32 " \
        "{%0, %1, %2, %3, %4, %5, %6, %7, " \
        " %8, %9, %10, %11, %12, %13, %14, %15, " \
        " %16, %17, %18, %19, %20, %21, %22, %23, " \
        " %24, %25, %26, %27, %28, %29, %30, %31}, [%32];" \
        : "=r"((r)[0]),  "=r"((r)[1]),  "=r"((r)[2]),  "=r"((r)[3]), \
          "=r"((r)[4]),  "=r"((r)[5]),  "=r"((r)[6]),  "=r"((r)[7]), \
          "=r"((r)[8]),  "=r"((r)[9]),  "=r"((r)[10]), "=r"((r)[11]), \
          "=r"((r)[12]), "=r"((r)[13]), "=r"((r)[14]), "=r"((r)[15]), \
          "=r"((r)[16]), "=r"((r)[17]), "=r"((r)[18]), "=r"((r)[19]), \
          "=r"((r)[20]), "=r"((r)[21]), "=r"((r)[22]), "=r"((r)[23]), \
          "=r"((r)[24]), "=r"((r)[25]), "=r"((r)[26]), "=r"((r)[27]), \
          "=r"((r)[28]), "=r"((r)[29]), "=r"((r)[30]), "=r"((r)[31]) \
        : "r"(addr))
#define MBAR_WAIT(mbar, parity) do {                                              \
    asm volatile(                                                                 \
        "{\n\t.reg .pred P1;\n\t"                                                 \
        "WAIT_LOOP_%=:\n\t"                                                       \
        "mbarrier.try_wait.parity.acquire.cta.shared::cta.b64 P1, [%0], %1, 0x989680;\n\t" \
        "@P1 bra.uni WAIT_DONE_%=;\n\t"                                           \
        "bra.uni WAIT_LOOP_%=;\n\t"                                               \
        "WAIT_DONE_%=:\n\t}"                                                      \
        :: "r"((uint32_t)(mbar)), "r"((uint32_t)(parity)) : "memory");            \
} while (0)
static constexpr uint32_t TC_IDESC_G =
    (1u << 4) | (2u << 7) | (2u << 10) | ((256u / 8) << 17) | ((128u / 16) << 24);
#endif

#define TCSTAGE 49152
#define TCB_OFF 16384

__global__ __launch_bounds__(128) void gemm_tc_tf32(
    const float* __restrict__ A, const float* __restrict__ B,
    float* __restrict__ C, int M, int N, int K)
{
#if HAS_TCGEN05
    extern __shared__ char smem[];
    const uint32_t sb = smem_u32(smem);
    const uint32_t ctrl = sb;
    const uint32_t data = (sb + 16 + 1023) & ~1023u;

    const int bm = blockIdx.y * 128;
    const int bn = blockIdx.x * 256;
    const int tid = threadIdx.x;
    const int wid = tid >> 5;
    const int lane = tid & 31;

    if (wid == 0) {
        asm volatile("tcgen05.alloc.cta_group::1.sync.aligned.shared::cta.b32 [%0], %1;"
            :: "r"(ctrl), "r"(256u) : "memory");
        asm volatile("tcgen05.relinquish_alloc_permit.cta_group::1.sync.aligned;");
    }
    __syncthreads();
    uint32_t tmem;
    asm volatile("ld.shared.b32 %0, [%1];" : "=r"(tmem) : "r"(ctrl));
    if (tid == 0)
        asm volatile("mbarrier.init.shared.b64 [%0], %1;" :: "r"(ctrl + 8), "r"(1u) : "memory");
    __syncthreads();

    const int nk = K / 32;

    auto load_chunk = [&](int it) {
        const uint32_t st = data + (uint32_t)(it & 1) * TCSTAGE;
        const int k0 = it * 32;
#pragma unroll
        for (int i = 0; i < 8; i++) {
            int e = tid + i * 128;
            int r = e >> 3, c = e & 7;
            uint32_t byte = (uint32_t)(r * 128 + c * 16);
            uint32_t sw = byte ^ ((byte >> 3) & 0x70u);
            cp_async16s(st + sw, A + (size_t)(bm + r) * K + k0 + c * 4);
        }
#pragma unroll
        for (int i = 0; i < 16; i++) {
            int e = tid + i * 128;
            int r = e >> 3, c = e & 7;
            uint32_t byte = (uint32_t)(r * 128 + c * 16);
            uint32_t sw = byte ^ ((byte >> 3) & 0x70u);
            cp_async16s(st + TCB_OFF + sw, B + (size_t)(bn + r) * K + k0 + c * 4);
        }
        cp_commit();
    };

    load_chunk(0);

    for (int it = 0; it < nk; it++) {
        asm volatile("cp.async.wait_group 0;");
        __syncthreads();
        asm volatile("fence.proxy.async.shared::cta;" ::: "memory");
        if (wid == 0) {
            const uint32_t st = data + (uint32_t)(it & 1) * TCSTAGE;
            uint64_t ad = make_desc_sw128(st);
            uint64_t bd = make_desc_sw128(st + TCB_OFF);
            if (elect_one_pred()) {
#pragma unroll
                for (int ks = 0; ks < 4; ks++)
                    tcgen05_mma_tf32_ss(tmem, ad + ks * 2, bd + ks * 2, TC_IDESC_G,
                                        (it != 0) || (ks != 0));
                asm volatile(
                    "tcgen05.commit.cta_group::1.mbarrier::arrive::one.shared::cluster.b64 [%0];"
                    :: "r"(ctrl + 8) : "memory");
            }
        }
        if (it + 1 < nk) load_chunk(it + 1);
        MBAR_WAIT(ctrl + 8, it & 1);
    }

    asm volatile("tcgen05.fence::after_thread_sync;" ::: "memory");

    {
        float* Crow = C + (size_t)(bm + wid * 32 + lane) * N + bn;
#pragma unroll
        for (int bt = 0; bt < 8; bt++) {
            uint32_t r32[32];
            TC_LD_X32(r32, tmem + bt * 32);
            asm volatile("tcgen05.wait::ld.sync.aligned;" ::: "memory");
#pragma unroll
            for (int q = 0; q < 8; q++) {
                float4 o;
                o.x = __uint_as_float(r32[q * 4 + 0]);
                o.y = __uint_as_float(r32[q * 4 + 1]);
                o.z = __uint_as_float(r32[q * 4 + 2]);
                o.w = __uint_as_float(r32[q * 4 + 3]);
                *(float4*)(Crow + bt * 32 + q * 4) = o;
            }
        }
    }

    __syncthreads();
    if (tid == 0)
        asm volatile("mbarrier.inval.shared.b64 [%0];" :: "r"(ctrl + 8) : "memory");
    __syncthreads();
    if (wid == 0)
        asm volatile("tcgen05.dealloc.cta_group::1.sync.aligned.b32 %0, %1;"
            :: "r"(tmem), "r"(256u));
#else
    (void)A; (void)B; (void)C; (void)M; (void)N; (void)K;
#endif
}

// ===========================================================================
// wmma GEMM fallback (non-'a' cubin only)
// ===========================================================================
#define GLDA 36
#define ASTG (128 * GLDA)
#define BSTG (256 * GLDA)

__global__ __launch_bounds__(256) void gemm_wmma_tf32(
    const float* __restrict__ A, const float* __restrict__ B,
    float* __restrict__ C, int M, int N, int K)
{
    if (g_use_tc) return;

    extern __shared__ float sg[];
    float* Asb[2] = { sg,            sg + ASTG };
    float* Bsb[2] = { sg + 2 * ASTG, sg + 2 * ASTG + BSTG };

    const int bm = blockIdx.y * 128;
    const int bn = blockIdx.x * 256;
    const int tid = threadIdx.x;
    const int wid = tid >> 5;
    const int warpM = wid & 1;
    const int warpN = wid >> 1;

    wmma::fragment<wmma::accumulator, 16, 16, 8, float> acc[4][4];
#pragma unroll
    for (int i = 0; i < 4; i++)
#pragma unroll
        for (int j = 0; j < 4; j++) wmma::fill_fragment(acc[i][j], 0.0f);

    const int nk = K / 32;
    auto load_chunk = [&](int it) {
        const int k0 = it * 32;
        float* As = Asb[it & 1];
        float* Bs = Bsb[it & 1];
#pragma unroll
        for (int i = 0; i < 4; i++) {
            int e = tid + i * 256;
            int r = e >> 3, c = (e & 7) * 4;
            cp_async16(As + r * GLDA + c, A + (size_t)(bm + r) * K + k0 + c);
        }
#pragma unroll
        for (int i = 0; i < 8; i++) {
            int e = tid + i * 256;
            int r = e >> 3, c = (e & 7) * 4;
            cp_async16(Bs + r * GLDA + c, B + (size_t)(bn + r) * K + k0 + c);
        }
        cp_commit();
    };
    load_chunk(0);
    for (int it = 0; it < nk; it++) {
        asm volatile("cp.async.wait_group 0;");
        __syncthreads();
        if (it + 1 < nk) load_chunk(it + 1);
        const float* As = Asb[it & 1];
        const float* Bs = Bsb[it & 1];
#pragma unroll
        for (int ks = 0; ks < 4; ks++) {
            wmma::fragment<wmma::matrix_a, 16, 16, 8, wmma::precision::tf32, wmma::row_major> af[4];
            wmma::fragment<wmma::matrix_b, 16, 16, 8, wmma::precision::tf32, wmma::col_major> bf[4];
#pragma unroll
            for (int i = 0; i < 4; i++)
                wmma::load_matrix_sync(af[i], As + (warpM * 64 + i * 16) * GLDA + ks * 8, GLDA);
#pragma unroll
            for (int j = 0; j < 4; j++)
                wmma::load_matrix_sync(bf[j], Bs + (warpN * 64 + j * 16) * GLDA + ks * 8, GLDA);
#pragma unroll
            for (int i = 0; i < 4; i++)
#pragma unroll
                for (int j = 0; j < 4; j++)
                    wmma::mma_sync(acc[i][j], af[i], bf[j], acc[i][j]);
        }
    }
#pragma unroll
    for (int i = 0; i < 4; i++)
#pragma unroll
        for (int j = 0; j < 4; j++)
            wmma::store_matrix_sync(
                C + (size_t)(bm + warpM * 64 + i * 16) * N + bn + warpN * 64 + j * 16,
                acc[i][j], N, wmma::mem_row_major);
}

// ---------------------------------------------------------------------------
// RoPE + bias + transpose; q scaled by 0.125*log2(e); tf32 stores
// ---------------------------------------------------------------------------
__global__ __launch_bounds__(256) void rope_bias_transpose_kernel(
    const float* __restrict__ rpe, const float* __restrict__ bq)
{
    __shared__ float cs[32], sn[32];
    const int m = blockIdx.x;   // l*8 + b
    const int l = m >> 3;
    const int b = m & 7;
    const int tid = threadIdx.x;
    if (tid < 32) {
        float a = rpe[l * 32 + tid];
        cs[tid] = cosf(a);
        sn[tid] = sinf(a);
    }
    __syncthreads();
    const float* src = g_qkv + (size_t)m * 3072;
    for (int r = tid; r < 3072; r += 256) {
        int which = r >> 10;
        int hh = (r >> 6) & 15;
        int d = r & 63;
        float x = src[r] + bq[r];
        float val;
        if (which < 2) {
            float xp = src[r ^ 1] + bq[r ^ 1];
            float c = cs[d & 31];
            float s = sn[d & 31];
            val = x * c + ((d & 1) ? xp : -xp) * s;
        } else {
            val = x;
        }
        if (which == 0) val *= 0.125f * 1.44269504f;   // scale * log2(e)
        float* dst = (which == 0) ? g_q : (which == 1) ? g_k : g_v;
        dst[(((size_t)(b * 16 + hh)) * 1024 + l) * 64 + d] = to_tf32(val);
    }
}

// ===========================================================================
// Flash attention, mma.sync tf32, SAFE-BOUND softmax with raw EX2:
//   p = ex2(s' - c_row), c_row = ||q'_row|| * kmax[bh]  (log2e folded in q)
// ===========================================================================
#define AKL 68
#define AVL 72
#define QSTG (128 * AKL)
#define KSTG (64 * AKL)
#define VSTG (64 * AVL)
#define ATT_FB_SMEM ((QSTG + 2 * KSTG + 2 * VSTG + 128) * (int)sizeof(float))

__global__ __launch_bounds__(128) void attn_tf32_reg()
{
    extern __shared__ float sm[];
    float* Qs = sm;
    float* Ksb[2] = { sm + QSTG,            sm + QSTG + KSTG };
    float* Vsb[2] = { sm + QSTG + 2 * KSTG, sm + QSTG + 2 * KSTG + VSTG };
    float* sNorm = sm + QSTG + 2 * KSTG + 2 * VSTG;   // 128 row shifts

    const int bh = blockIdx.x;
    const int b = bh >> 4;
    const int h = bh & 15;
    const int qt = blockIdx.y;
    const int tid = threadIdx.x;
    const int w = tid >> 5;
    const int lane = tid & 31;
    const int g = lane >> 2;
    const int t = lane & 3;

    const float* Kg = g_k + (size_t)bh * 65536;
    const float* Vg = g_v + (size_t)bh * 65536;

    auto load_kv = [&](int kt) {
        float* Kd = Ksb[kt & 1];
        float* Vd = Vsb[kt & 1];
        const size_t off = (size_t)kt * 4096;
#pragma unroll
        for (int i = 0; i < 8; i++) {
            int e = tid + i * 128;
            int r = e >> 4, c = (e & 15) * 4;
            cp_async16(Kd + r * AKL + c, Kg + off + (size_t)r * 64 + c);
            cp_async16(Vd + r * AVL + c, Vg + off + (size_t)r * 64 + c);
        }
        cp_commit();
    };
    load_kv(0);

    {
        const float* Qg = g_q + ((size_t)bh * 1024 + qt * 128) * 64;
#pragma unroll
        for (int i = 0; i < 16; i++) {
            int e = tid + i * 128;
            int r = e >> 4, c = (e & 15) * 4;
            float4 v = *(const float4*)(Qg + r * 64 + c);
            *(float4*)(Qs + r * AKL + c) = v;
        }
    }
    __syncthreads();

    // per-row softmax shift: sNorm[r] = ||q'_r|| * kmax + eps
    {
        float qq = 0.f;
        const float4* qr = (const float4*)(Qs + tid * AKL);
#pragma unroll
        for (int f = 0; f < 16; f++) {
            float4 v = qr[f];
            qq += v.x * v.x + v.y * v.y + v.z * v.z + v.w * v.w;
        }
        sNorm[tid] = sqrtf(qq) * g_kmax[bh] + 1e-3f;
    }

    unsigned qa[2][8][4];
#pragma unroll
    for (int rf = 0; rf < 2; rf++) {
        const float* Qw = Qs + (w * 32 + rf * 16) * AKL;
#pragma unroll
        for (int ks = 0; ks < 8; ks++) {
            qa[rf][ks][0] = __float_as_uint(Qw[g * AKL + ks * 8 + t]);
            qa[rf][ks][1] = __float_as_uint(Qw[(g + 8) * AKL + ks * 8 + t]);
            qa[rf][ks][2] = __float_as_uint(Qw[g * AKL + ks * 8 + t + 4]);
            qa[rf][ks][3] = __float_as_uint(Qw[(g + 8) * AKL + ks * 8 + t + 4]);
        }
    }
    __syncthreads();   // norms visible; Qs becomes P strips

    float csh[2][2];
#pragma unroll
    for (int rf = 0; rf < 2; rf++) {
        csh[rf][0] = sNorm[w * 32 + rf * 16 + g];
        csh[rf][1] = sNorm[w * 32 + rf * 16 + 8 + g];
    }

    float o[2][8][4];
#pragma unroll
    for (int rf = 0; rf < 2; rf++)
#pragma unroll
        for (int j = 0; j < 8; j++)
            o[rf][j][0] = o[rf][j][1] = o[rf][j][2] = o[rf][j][3] = 0.f;
    float psum[2][2] = {{0.f, 0.f}, {0.f, 0.f}};

    const int qrow = qt * 128 + w * 32 + g;
    float* Pw = Qs + (w * 32) * AKL;

    for (int kt = 0; kt < 16; kt++) {
        asm volatile("cp.async.wait_group 0;");
        __syncthreads();
        if (kt + 1 < 16) load_kv(kt + 1);

        const float* Ks = Ksb[kt & 1];
        const float* Vs = Vsb[kt & 1];

        // S = Q K^T
        float s[2][8][4];
#pragma unroll
        for (int j = 0; j < 8; j++) {
            s[0][j][0] = s[0][j][1] = s[0][j][2] = s[0][j][3] = 0.f;
            s[1][j][0] = s[1][j][1] = s[1][j][2] = s[1][j][3] = 0.f;
#pragma unroll
            for (int ks = 0; ks < 8; ks++) {
                unsigned b0 = __float_as_uint(Ks[(j * 8 + g) * AKL + ks * 8 + t]);
                unsigned b1 = __float_as_uint(Ks[(j * 8 + g) * AKL + ks * 8 + t + 4]);
                mma8(s[0][j], qa[0][ks], b0, b1);
                mma8(s[1][j], qa[1][ks], b0, b1);
            }
        }

        // safe-bound softmax: p = ex2(s - c) if mask else 0  (single MUFU)
        const size_t mbi = ((size_t)b * 16 + kt) * 1024;
#pragma unroll
        for (int rf = 0; rf < 2; rf++) {
            const unsigned long long mb0 = g_maskbits[mbi + qrow + rf * 16];
            const unsigned long long mb1 = g_maskbits[mbi + qrow + rf * 16 + 8];
            float* Prf = Pw + rf * 16 * AKL;
#pragma unroll
            for (int j = 0; j < 8; j++) {
                int c0 = j * 8 + t * 2;
                float p0 = ((mb0 >> c0) & 1ULL)       ? ex2_fast(s[rf][j][0] - csh[rf][0]) : 0.f;
                float p1 = ((mb0 >> (c0 + 1)) & 1ULL) ? ex2_fast(s[rf][j][1] - csh[rf][0]) : 0.f;
                float p2 = ((mb1 >> c0) & 1ULL)       ? ex2_fast(s[rf][j][2] - csh[rf][1]) : 0.f;
                float p3 = ((mb1 >> (c0 + 1)) & 1ULL) ? ex2_fast(s[rf][j][3] - csh[rf][1]) : 0.f;
                psum[rf][0] += p0 + p1;
                psum[rf][1] += p2 + p3;
                *(float2*)(Prf + g * AKL + j * 8 + t * 2) =
                    make_float2(to_tf32(p0), to_tf32(p1));
                *(float2*)(Prf + (g + 8) * AKL + j * 8 + t * 2) =
                    make_float2(to_tf32(p2), to_tf32(p3));
            }
        }
        __syncwarp();

        // O += P V
#pragma unroll
        for (int ks = 0; ks < 8; ks++) {
            unsigned pa[2][4];
#pragma unroll
            for (int rf = 0; rf < 2; rf++) {
                const float* Prf = Pw + rf * 16 * AKL;
                pa[rf][0] = __float_as_uint(Prf[g * AKL + ks * 8 + t]);
                pa[rf][1] = __float_as_uint(Prf[(g + 8) * AKL + ks * 8 + t]);
                pa[rf][2] = __float_as_uint(Prf[g * AKL + ks * 8 + t + 4]);
                pa[rf][3] = __float_as_uint(Prf[(g + 8) * AKL + ks * 8 + t + 4]);
            }
#pragma unroll
            for (int j = 0; j < 8; j++) {
                unsigned b0 = __float_as_uint(Vs[(ks * 8 + t) * AVL + j * 8 + g]);
                unsigned b1 = __float_as_uint(Vs[(ks * 8 + t + 4) * AVL + j * 8 + g]);
                mma8(o[0][j], pa[0], b0, b1);
                mma8(o[1][j], pa[1], b0, b1);
            }
        }
        __syncwarp();
    }

    // single end-of-kernel row-sum reduction (quad)
#pragma unroll
    for (int rf = 0; rf < 2; rf++)
#pragma unroll
        for (int hf = 0; hf < 2; hf++) {
            float v = psum[rf][hf];
            v += __shfl_xor_sync(0xffffffffu, v, 1);
            v += __shfl_xor_sync(0xffffffffu, v, 2);
            psum[rf][hf] = v;
        }

#pragma unroll
    for (int rf = 0; rf < 2; rf++) {
        const float inv0 = 1.f / psum[rf][0], inv1 = 1.f / psum[rf][1];
        const int lq0 = qt * 128 + w * 32 + rf * 16 + g;
#pragma unroll
        for (int j = 0; j < 8; j++) {
            *(float2*)(g_attn + ((size_t)lq0 * 8 + b) * 1024 + h * 64 + j * 8 + t * 2) =
                make_float2(to_tf32(o[rf][j][0] * inv0), to_tf32(o[rf][j][1] * inv0));
            *(float2*)(g_attn + ((size_t)(lq0 + 8) * 8 + b) * 1024 + h * 64 + j * 8 + t * 2) =
                make_float2(to_tf32(o[rf][j][2] * inv1), to_tf32(o[rf][j][3] * inv1));
        }
    }
}

// ---------------------------------------------------------------------------
// Final bias add
// ---------------------------------------------------------------------------
__global__ __launch_bounds__(256) void bias_add_kernel(float* __restrict__ out,
                                                       const float* __restrict__ bo)
{
    const int m = blockIdx.x;
    const int c = threadIdx.x * 4;
    float4 o = *(float4*)(out + (size_t)m * 1024 + c);
    float4 bb = *(const float4*)(bo + c);
    o.x += bb.x; o.y += bb.y; o.z += bb.z; o.w += bb.w;
    *(float4*)(out + (size_t)m * 1024 + c) = o;
}

// ---------------------------------------------------------------------------
// Launch
// ---------------------------------------------------------------------------
extern "C" void kernel_launch(void* const* d_in, const int* in_sizes, int n_in,
                              void* d_out, int out_size)
{
    const float* hs   = (const float*)d_in[0];
    const float* rpe  = (const float*)d_in[1];
    const void* maskp = d_in[2];
    const float* Wqkv = (const float*)d_in[3];
    const float* bqkv = (const float*)d_in[4];
    const float* Wo   = (const float*)d_in[5];
    const float* bo   = (const float*)d_in[6];
    float* out        = (float*)d_out;

    float *hs_p, *wqkv_p, *wo_p, *qkv_p, *attn_p;
    cudaGetSymbolAddress((void**)&hs_p, g_hs);
    cudaGetSymbolAddress((void**)&wqkv_p, g_wqkv);
    cudaGetSymbolAddress((void**)&wo_p, g_wo);
    cudaGetSymbolAddress((void**)&qkv_p, g_qkv);
    cudaGetSymbolAddress((void**)&attn_p, g_attn);

    probe_tc_kernel<<<1, 32>>>();
    detect_mask_mode_kernel<<<1, 256>>>((const unsigned char*)maskp);
    convert_mask_bits_kernel<<<131072 / 256, 256>>>(maskp);
    tf32_round_kernel<<<(8388608 / 4) / 256, 256>>>(hs_p, hs, 8388608 / 4);
    tf32_round_kernel<<<(3145728 / 4) / 256, 256>>>(wqkv_p, Wqkv, 3145728 / 4);
    tf32_round_kernel<<<(1048576 / 4) / 256, 256>>>(wo_p, Wo, 1048576 / 4);

    const int tc_smem = 2048 + 2 * TCSTAGE;
    const int wm_smem = 2 * (ASTG + BSTG) * (int)sizeof(float);
    cudaFuncSetAttribute(gemm_tc_tf32,
                         cudaFuncAttributeMaxDynamicSharedMemorySize, tc_smem);
    cudaFuncSetAttribute(gemm_wmma_tf32,
                         cudaFuncAttributeMaxDynamicSharedMemorySize, wm_smem);

    // Stage 1: QKV projection (dual path)
    {
        dim3 grid(3072 / 256, 8192 / 128);
        gemm_tc_tf32<<<grid, 128, tc_smem>>>(hs_p, wqkv_p, qkv_p, 8192, 3072, 1024);
        gemm_wmma_tf32<<<grid, 256, wm_smem>>>(hs_p, wqkv_p, qkv_p, 8192, 3072, 1024);
    }

    // Stage 2: RoPE + bqkv + transpose ; kmax
    rope_bias_transpose_kernel<<<8192, 256>>>(rpe, bqkv);
    kmax_kernel<<<128, 256>>>();

    // Stage 3: attention (mma.sync, safe-bound softmax, fast EX2)
    {
        cudaFuncSetAttribute(attn_tf32_reg,
                             cudaFuncAttributeMaxDynamicSharedMemorySize, ATT_FB_SMEM);
        dim3 grid(128, 8);
        attn_tf32_reg<<<grid, 128, ATT_FB_SMEM>>>();
    }

    // Stage 4: output projection (dual path) + bias
    {
        dim3 grid(1024 / 256, 8192 / 128);
        gemm_tc_tf32<<<grid, 128, tc_smem>>>(attn_p, wo_p, out, 8192, 1024, 1024);
        gemm_wmma_tf32<<<grid, 256, wm_smem>>>(attn_p, wo_p, out, 8192, 1024, 1024);
        bias_add_kernel<<<8192, 256>>>(out, bo);
    }
}